// round 3
// baseline (speedup 1.0000x reference)
#include <cuda_runtime.h>
#include <cuda_bf16.h>

// Problem constants
#define BATCH 32
#define CIN   256
#define COUT  256
#define HH    49
#define WW    49
#define NPIX  (HH * WW)          // 2401
#define NDIR  7

// GEMM tiling
#define BM 64
#define BN 64
#define BK 8

// Transposed weight scratch: wt[n][c][o]  (7*256*256 floats = 1.75 MB)
__device__ float g_wt[NDIR * CIN * COUT];

__global__ void hex_transpose_w(const float* __restrict__ w) {
    int idx = blockIdx.x * blockDim.x + threadIdx.x;
    if (idx < NDIR * CIN * COUT) {
        int o = idx & 255;
        int c = (idx >> 8) & 255;
        int n = idx >> 16;
        // weight layout [O, C, 7]
        g_wt[idx] = w[o * (CIN * NDIR) + c * NDIR + n];
    }
}

__global__ __launch_bounds__(256, 4)
void hexconv_gemm(const float* __restrict__ x,
                  const float* __restrict__ bias,
                  float* __restrict__ out) {
    // DIRS (dy, dx): matches reference
    const int DY[NDIR] = {0, 1, 0, -1, -1, 0, 1};
    const int DX[NDIR] = {0, 0, 1,  1,  0, -1, -1};

    __shared__ float As[BK][BM];
    __shared__ float Bs[BK][BN];

    const int b  = blockIdx.z;
    const int p0 = blockIdx.x * BM;
    const int o0 = blockIdx.y * BN;
    const int tid = threadIdx.x;

    // Cooperative load decomposition: element e = tid -> (kk = e/64, m = e%64),
    // second element e+256 -> (kk+4, same m).
    const int lk = tid >> 6;     // 0..3
    const int lm = tid & 63;     // 0..63

    // Pixel handled by this thread's A loads
    const int p  = p0 + lm;
    const int ph = p / WW;
    const int pw = p - ph * WW;
    const bool pvalid = (p < NPIX);

    const float* xb = x + (size_t)b * CIN * NPIX;

    // Compute-thread mapping: 16x16 grid of threads, 4x4 outputs each
    const int ty = tid >> 4;     // 0..15 -> pixel group
    const int tx = tid & 15;     // 0..15 -> output-channel group

    float acc[4][4];
#pragma unroll
    for (int i = 0; i < 4; i++)
#pragma unroll
        for (int j = 0; j < 4; j++) acc[i][j] = 0.f;

#pragma unroll
    for (int n = 0; n < NDIR; n++) {
        const int hh = ph + DY[n];
        const int ww = pw + DX[n];
        // source in-bounds + source hex mask (24 <= h+w <= 72)
        const bool av = pvalid &&
                        ((unsigned)hh < HH) && ((unsigned)ww < WW) &&
                        (hh + ww >= 24) && (hh + ww <= 72);
        const int psrc = av ? (hh * WW + ww) : 0;
        const float* xsrc = xb + psrc;
        const float* wsrc = g_wt + (n * CIN) * COUT + o0;

        for (int c0 = 0; c0 < CIN; c0 += BK) {
            // A tile: As[kk][m] = x[b, c0+kk, psrc(m)]
            float a0 = av ? xsrc[(size_t)(c0 + lk) * NPIX]     : 0.f;
            float a1 = av ? xsrc[(size_t)(c0 + lk + 4) * NPIX] : 0.f;
            As[lk][lm]     = a0;
            As[lk + 4][lm] = a1;
            // B tile: Bs[kk][nn] = wt[n, c0+kk, o0+nn]  (coalesced)
            Bs[lk][lm]     = wsrc[(size_t)(c0 + lk) * COUT + lm];
            Bs[lk + 4][lm] = wsrc[(size_t)(c0 + lk + 4) * COUT + lm];
            __syncthreads();

#pragma unroll
            for (int kk = 0; kk < BK; kk++) {
                float av4[4], bv4[4];
#pragma unroll
                for (int i = 0; i < 4; i++) av4[i] = As[kk][ty * 4 + i];
#pragma unroll
                for (int j = 0; j < 4; j++) bv4[j] = Bs[kk][tx * 4 + j];
#pragma unroll
                for (int i = 0; i < 4; i++)
#pragma unroll
                    for (int j = 0; j < 4; j++)
                        acc[i][j] += av4[i] * bv4[j];
            }
            __syncthreads();
        }
    }

    // Epilogue: destination hex mask + bias; write everything (masked -> 0)
#pragma unroll
    for (int i = 0; i < 4; i++) {
        const int pp = p0 + ty * 4 + i;
        if (pp >= NPIX) continue;
        const int h = pp / WW;
        const int w = pp - h * WW;
        const bool om = (h + w >= 24) && (h + w <= 72);
#pragma unroll
        for (int j = 0; j < 4; j++) {
            const int o = o0 + tx * 4 + j;
            const float v = om ? (acc[i][j] + bias[o]) : 0.f;
            out[((size_t)b * COUT + o) * NPIX + pp] = v;
        }
    }
}

extern "C" void kernel_launch(void* const* d_in, const int* in_sizes, int n_in,
                              void* d_out, int out_size) {
    const float* x    = (const float*)d_in[0];
    const float* wgt  = (const float*)d_in[1];
    const float* bias = (const float*)d_in[2];
    float* out = (float*)d_out;

    (void)in_sizes; (void)n_in; (void)out_size;

    // 1) transpose weight [O,C,7] -> wt[n][c][o] for coalesced GEMM B loads
    {
        int total = NDIR * CIN * COUT;
        hex_transpose_w<<<(total + 255) / 256, 256>>>(wgt);
    }

    // 2) implicit GEMM
    {
        dim3 grid((NPIX + BM - 1) / BM,   // 38 pixel tiles
                  COUT / BN,              // 4 output tiles
                  BATCH);                 // 32
        hexconv_gemm<<<grid, 256>>>(x, bias, out);
    }
}

// round 5
// speedup vs baseline: 2.0651x; 2.0651x over previous
#include <cuda_runtime.h>
#include <cuda_bf16.h>
#include <cstdint>

// ---------------- problem constants ----------------
#define BATCH 32
#define CIN   256
#define COUT  256
#define HH    49
#define WW    49
#define NPIX  2401
#define NDIR  7

// ---------------- GEMM tiling ----------------
#define BM 64
#define BN 256
#define BK 32
#define RS 80                      // smem row stride bytes (32 bf16 = 64B + 16B pad)
#define A_BYTES (BM * RS)          // 5120
#define B_BYTES (BN * RS)          // 20480
#define STAGE   (2 * A_BYTES + 2 * B_BYTES)   // 51200
#define SMEM_BYTES (2 * STAGE)                // 102400
#define NCHUNK  (NDIR * (CIN / BK))           // 56

// ---------------- scratch (static __device__, allocation-guard safe) ----------------
__device__ __align__(16) __nv_bfloat16 g_xt_hi[(size_t)BATCH * NPIX * CIN];
__device__ __align__(16) __nv_bfloat16 g_xt_lo[(size_t)BATCH * NPIX * CIN];
__device__ __align__(16) __nv_bfloat16 g_w_hi[NDIR * COUT * CIN];
__device__ __align__(16) __nv_bfloat16 g_w_lo[NDIR * COUT * CIN];

__constant__ int cDY[NDIR] = {0, 1, 0, -1, -1, 0, 1};
__constant__ int cDX[NDIR] = {0, 0, 1,  1,  0, -1, -1};

// ---------------- PTX helpers (portable: sm_80-level, no "a" features) ----------------
__device__ __forceinline__ void cpa16(uint32_t dst, const void* src, int szbytes) {
    asm volatile("cp.async.cg.shared.global [%0], [%1], 16, %2;"
                 :: "r"(dst), "l"(src), "r"(szbytes) : "memory");
}
#define CP_COMMIT() asm volatile("cp.async.commit_group;" ::: "memory")
#define CP_WAIT1()  asm volatile("cp.async.wait_group 1;" ::: "memory")

#define LDSM4(r, addr) \
    asm volatile("ldmatrix.sync.aligned.m8n8.x4.shared.b16 {%0,%1,%2,%3}, [%4];" \
                 : "=r"((r)[0]), "=r"((r)[1]), "=r"((r)[2]), "=r"((r)[3]) : "r"(addr))

#define MMA(d, a, bp) \
    asm volatile("mma.sync.aligned.m16n8k16.row.col.f32.bf16.bf16.f32 " \
                 "{%0,%1,%2,%3}, {%4,%5,%6,%7}, {%8,%9}, {%0,%1,%2,%3};" \
                 : "+f"((d)[0]), "+f"((d)[1]), "+f"((d)[2]), "+f"((d)[3]) \
                 : "r"((a)[0]), "r"((a)[1]), "r"((a)[2]), "r"((a)[3]), \
                   "r"((bp)[0]), "r"((bp)[1]))

// ---------------- preprocessing ----------------
// x [B,C,H,W] fp32 --(hex source mask, transpose, bf16 hi/lo split)--> xt [b][p][c]
__global__ void split_x_kernel(const float* __restrict__ x) {
    __shared__ float t[32][33];
    const int pt = blockIdx.x, ct = blockIdx.y, b = blockIdx.z;
    const int p00 = pt * 32, c00 = ct * 32;
    const int tx = threadIdx.x & 31;
    const int ty = threadIdx.x >> 5;

#pragma unroll
    for (int k = 0; k < 4; ++k) {
        const int c = c00 + ty + k * 8;
        const int p = p00 + tx;
        float v = 0.f;
        if (p < NPIX) {
            const int h = p / WW, w = p - (p / WW) * WW;
            if (h + w >= 24 && h + w <= 72)
                v = x[((size_t)b * CIN + c) * NPIX + p];
        }
        t[ty + k * 8][tx] = v;
    }
    __syncthreads();
#pragma unroll
    for (int k = 0; k < 4; ++k) {
        const int p = p00 + ty + k * 8;
        if (p >= NPIX) continue;
        const int c = c00 + tx;
        const float v = t[tx][ty + k * 8];
        const __nv_bfloat16 hi = __float2bfloat16(v);
        const float r = v - __bfloat162float(hi);
        const size_t o = ((size_t)b * NPIX + p) * CIN + c;
        g_xt_hi[o] = hi;
        g_xt_lo[o] = __float2bfloat16(r);
    }
}

// weight [O,C,7] fp32 -> [n][o][c] bf16 hi/lo
__global__ void split_w_kernel(const float* __restrict__ w) {
    const int idx = blockIdx.x * blockDim.x + threadIdx.x;
    if (idx >= NDIR * COUT * CIN) return;
    const int c = idx & 255;
    const int o = (idx >> 8) & 255;
    const int n = idx >> 16;
    const float v = w[o * (CIN * NDIR) + c * NDIR + n];
    const __nv_bfloat16 hi = __float2bfloat16(v);
    const float r = v - __bfloat162float(hi);
    g_w_hi[idx] = hi;
    g_w_lo[idx] = __float2bfloat16(r);
}

// ---------------- main warp-MMA implicit-GEMM kernel ----------------
__global__ __launch_bounds__(256, 2)
void hexconv_mma(const float* __restrict__ bias, float* __restrict__ out) {
    extern __shared__ char smem[];
    const uint32_t sb = (uint32_t)__cvta_generic_to_shared(smem);
    const int tid  = threadIdx.x;
    const int lane = tid & 31;
    const int wid  = tid >> 5;
    const int wm   = wid & 1;      // 2 M groups of 32
    const int wn   = wid >> 1;     // 4 N groups of 64
    const int p0   = blockIdx.x * BM;
    const int b    = blockIdx.y;

    // A-load geometry: thread -> (row am = tid/4, 16B chunk akc = tid%4)
    const int am  = tid >> 2;
    const int akc = tid & 3;
    const int ap  = p0 + am;
    const int aph = ap / WW;
    const int apw = ap - aph * WW;
    const bool apv = (ap < NPIX);

    float acc[2][8][4];
#pragma unroll
    for (int i = 0; i < 2; ++i)
#pragma unroll
        for (int j = 0; j < 8; ++j)
#pragma unroll
            for (int r = 0; r < 4; ++r) acc[i][j][r] = 0.f;

    auto load_chunk = [&](int ch, int s) {
        const int nd = ch >> 3;
        const int c0 = (ch & 7) << 5;
        const uint32_t st = sb + (uint32_t)s * STAGE;
        // A (hi+lo): shifted, bounds-masked via src-size=0 zero fill
        const int hh = aph + cDY[nd];
        const int ww = apw + cDX[nd];
        const bool av = apv && ((unsigned)hh < HH) && ((unsigned)ww < WW);
        const int ps = av ? (hh * WW + ww) : 0;
        const size_t abase = ((size_t)b * NPIX + ps) * CIN + c0 + akc * 8;
        const int asz = av ? 16 : 0;
        cpa16(st + am * RS + akc * 16,           g_xt_hi + abase, asz);
        cpa16(st + A_BYTES + am * RS + akc * 16, g_xt_lo + abase, asz);
        // B (hi+lo): row o = tid, 64B contiguous k
        const size_t bbase = ((size_t)nd * COUT + tid) * CIN + c0;
        const uint32_t bdst = st + 2 * A_BYTES + tid * RS;
#pragma unroll
        for (int j = 0; j < 4; ++j) {
            cpa16(bdst + j * 16,           g_w_hi + bbase + j * 8, 16);
            cpa16(bdst + B_BYTES + j * 16, g_w_lo + bbase + j * 8, 16);
        }
    };

    auto compute_chunk = [&](int s) {
        const uint32_t st = sb + (uint32_t)s * STAGE;
        const uint32_t Ah = st;
        const uint32_t Bh = st + 2 * A_BYTES;
#pragma unroll
        for (int ks = 0; ks < 2; ++ks) {
            const int kb = ks * 32;   // 16 bf16 = 32 bytes
            uint32_t ah[2][4], al[2][4], bb[4][4];
            const uint32_t aaddr = Ah + (uint32_t)((wm * 32 + (lane & 15)) * RS)
                                   + kb + ((lane >> 4) << 4);
            LDSM4(ah[0], aaddr);
            LDSM4(ah[1], aaddr + 16 * RS);
            LDSM4(al[0], aaddr + A_BYTES);
            LDSM4(al[1], aaddr + A_BYTES + 16 * RS);
            const uint32_t baddr = Bh + (uint32_t)((wn * 64 + ((lane >> 4) << 3) + (lane & 7)) * RS)
                                   + kb + (((lane >> 3) & 1) << 4);
#pragma unroll
            for (int g = 0; g < 4; ++g) LDSM4(bb[g], baddr + g * 16 * RS);
            // acc += Ah*Bh + Al*Bh
#pragma unroll
            for (int mi = 0; mi < 2; ++mi)
#pragma unroll
                for (int ni = 0; ni < 8; ++ni) {
                    const uint32_t* bp = &bb[ni >> 1][(ni & 1) * 2];
                    MMA(acc[mi][ni], ah[mi], bp);
                    MMA(acc[mi][ni], al[mi], bp);
                }
            // reload B = Bl, acc += Ah*Bl
#pragma unroll
            for (int g = 0; g < 4; ++g) LDSM4(bb[g], baddr + B_BYTES + g * 16 * RS);
#pragma unroll
            for (int mi = 0; mi < 2; ++mi)
#pragma unroll
                for (int ni = 0; ni < 8; ++ni) {
                    const uint32_t* bp = &bb[ni >> 1][(ni & 1) * 2];
                    MMA(acc[mi][ni], ah[mi], bp);
                }
        }
    };

    // ---------------- pipelined mainloop ----------------
    load_chunk(0, 0);
    CP_COMMIT();
    for (int ch = 0; ch < NCHUNK; ++ch) {
        if (ch + 1 < NCHUNK) load_chunk(ch + 1, (ch + 1) & 1);
        CP_COMMIT();
        CP_WAIT1();
        __syncthreads();
        compute_chunk(ch & 1);
        __syncthreads();
    }

    // ---------------- epilogue: bias + dest hex mask ----------------
    float bv[16];
#pragma unroll
    for (int ni = 0; ni < 8; ++ni)
#pragma unroll
        for (int j = 0; j < 2; ++j)
            bv[ni * 2 + j] = bias[wn * 64 + ni * 8 + (lane & 3) * 2 + j];

#pragma unroll
    for (int mi = 0; mi < 2; ++mi)
#pragma unroll
        for (int rh = 0; rh < 2; ++rh) {
            const int m = wm * 32 + mi * 16 + (lane >> 2) + rh * 8;
            const int p = p0 + m;
            if (p >= NPIX) continue;
            const int h = p / WW, w = p - (p / WW) * WW;
            const bool om = (h + w >= 24) && (h + w <= 72);
#pragma unroll
            for (int ni = 0; ni < 8; ++ni)
#pragma unroll
                for (int j = 0; j < 2; ++j) {
                    const int o = wn * 64 + ni * 8 + (lane & 3) * 2 + j;
                    const float v = om ? (acc[mi][ni][rh * 2 + j] + bv[ni * 2 + j]) : 0.f;
                    out[((size_t)b * COUT + o) * NPIX + p] = v;
                }
        }
}

// ---------------- launch ----------------
extern "C" void kernel_launch(void* const* d_in, const int* in_sizes, int n_in,
                              void* d_out, int out_size) {
    const float* x    = (const float*)d_in[0];
    const float* wgt  = (const float*)d_in[1];
    const float* bias = (const float*)d_in[2];
    float* out = (float*)d_out;
    (void)in_sizes; (void)n_in; (void)out_size;

    cudaFuncSetAttribute(hexconv_mma, cudaFuncAttributeMaxDynamicSharedMemorySize, SMEM_BYTES);

    split_x_kernel<<<dim3(76, 8, BATCH), 256>>>(x);
    split_w_kernel<<<(NDIR * COUT * CIN + 255) / 256, 256>>>(wgt);

    hexconv_mma<<<dim3((NPIX + BM - 1) / BM, BATCH), 256, SMEM_BYTES>>>(bias, out);
}